// round 11
// baseline (speedup 1.0000x reference)
#include <cuda_runtime.h>
#include <cuda_bf16.h>

// Sinkhorn EMD, N=M=1024, D=3, eps=0.01, iters read from input (3000).
// Persistent kernel, 128 CTAs x 256 threads; warp w of CTA b owns row b*8+w.
//
// Sync skeleton is the PROVEN R10 design (passed, 16.21ms, rel_err 1.1e-7):
// tree arrivals (16 group counters + root, parity double-buffered), monotone
// d_gen release, R9-verbatim fence placement (writer __threadfence before
// arrivals; acquire __threadfence + IVALL after spin). Cost matrix in SMEM.
//
// NEW in this round: EXACT fixed-point / period-2 early exit.
//   fp32 Sinkhorn is a deterministic map; if f is bitwise unchanged vs the
//   previous iteration, all later iterations are no-ops => break with the
//   exact same final state as running all 3000. If f equals f from TWO
//   iterations ago (bitwise period-2 limit cycle), the final state is the
//   one matching the parity of (iters-1), so finish at that parity and break.
//   Detection every 8th iteration via two global flag words holding a
//   launch-unique token (base+it); writes are covered by the barrier's
//   writer fence, reads happen post-barrier (post-IVALL) => grid-uniform.
//
// Math in the exp2 domain scaled by S = log2(e)/eps (S*eps*ln2 == 1,
// S*eps*ln(1024) == 10):  S*f_row = -10 - m - log2(sum_j exp2(args_j - m)).

#define Nn      1024
#define NCTA    128
#define NTH     256
#define S_CONST 144.26950408889634074f   // log2(e)/eps, eps = 0.01
#define INV_S   0.0069314718055994531f   // eps*ln2 = 1/S
#define CHECK_MASK 7                     // convergence check every 8 iterations

#define SMEM_BYTES (8 * 1024 * 2 * 4)    // sSC + sSCT = 64 KB

__device__ __align__(16) float d_Sf[Nn];      // S * f
__device__ __align__(16) float d_Sg[Nn];      // S * g
__device__ __align__(16) float d_rowsum[Nn];
__device__ unsigned d_gen = 0;                 // monotone release word
__device__ unsigned d_grp[2][16 * 64];         // parity-buffered group counters (256B stride)
__device__ unsigned d_root[2 * 64];            // parity-buffered root counters
__device__ unsigned d_flag1 = 0;               // "f changed vs 1 iter ago" token
__device__ unsigned d_flag2 = 0;               // "f changed vs 2 iters ago" token

__device__ __forceinline__ float ex2f(float x) {
    float r;
    asm("ex2.approx.ftz.f32 %0, %1;" : "=f"(r) : "f"(x));
    return r;
}

// Tree grid barrier (R10-verbatim; proven). n_abs = base-adjusted index.
__device__ __forceinline__ void tree_sync(unsigned n_abs, int gi) {
    __syncthreads();
    if (threadIdx.x == 0) {
        __threadfence();                              // writer release
        const int pp = (int)(n_abs & 1u);
        unsigned gprev = atomicAdd(&d_grp[pp][gi << 6], 1u);
        if (gprev == 7u) {                            // group leader
            unsigned rprev = atomicAdd(&d_root[pp << 6], 1u);
            d_grp[pp][gi << 6] = 0u;                  // drained by trailing fence
            if (rprev == 15u) {                       // root leader: release
                d_root[pp << 6] = 0u;
                *(volatile unsigned*)&d_gen = n_abs + 1u;
            }
        }
        while (*(volatile unsigned*)&d_gen < n_abs + 1u) { }
        __threadfence();                              // acquire + IVALL
    }
    __syncthreads();
}

// One Sinkhorn half-reduction; returns the warp-uniform result value.
//   ret = -10 - m - log2( sum_j exp2( din[j] - sC[w][j] - m ) )
template <bool HASG>
__device__ __forceinline__ float half_reduce(const float* __restrict__ sC,
                                             const float* __restrict__ din,
                                             int w, int lane) {
    const float4* c4 = (const float4*)(sC + (w << 10));
    const float4* g4 = (const float4*)din;
    float args[32];
    float m = -3.4e38f;
#pragma unroll
    for (int k = 0; k < 8; k++) {
        const int idx = (k << 5) + lane;
        const float4 c = c4[idx];                       // LDS.128, conflict-free
        const float4 g = HASG ? g4[idx]                 // plain LDG.128 (fresh post-IVALL)
                              : make_float4(0.f, 0.f, 0.f, 0.f);
        const float a0 = g.x - c.x;
        const float a1 = g.y - c.y;
        const float a2 = g.z - c.z;
        const float a3 = g.w - c.w;
        args[4 * k + 0] = a0; args[4 * k + 1] = a1;
        args[4 * k + 2] = a2; args[4 * k + 3] = a3;
        m = fmaxf(m, fmaxf(fmaxf(a0, a1), fmaxf(a2, a3)));
    }
#pragma unroll
    for (int off = 16; off; off >>= 1)
        m = fmaxf(m, __shfl_xor_sync(0xffffffffu, m, off));
    float sum = 0.f;
#pragma unroll
    for (int k = 0; k < 32; k++) sum += ex2f(args[k] - m);
#pragma unroll
    for (int off = 16; off; off >>= 1)
        sum += __shfl_xor_sync(0xffffffffu, sum, off);
    return -10.0f - m - __log2f(sum);
}

__global__ void __launch_bounds__(NTH, 1)
emd_kernel(const float* __restrict__ tgt,    // [1024,3]
           const float* __restrict__ outp,   // [1024,3]
           const int*   __restrict__ iters_ptr,
           float*       __restrict__ out) {
    extern __shared__ __align__(16) float smem[];
    float* sSC  = smem;                // [8][1024]  S*C rows
    float* sSCT = smem + 8 * 1024;     // [8][1024]  S*C^T rows
    __shared__ float red[NTH];

    const int tid  = threadIdx.x;
    const int w    = tid >> 5;
    const int lane = tid & 31;
    const int bid  = (int)blockIdx.x;
    const int gi   = bid >> 3;
    const int row  = (bid << 3) + w;

    // Per-launch monotone-gen base. Safe: d_gen cannot advance before every
    // CTA (including this one) arrives at barrier 1, which is after this read.
    unsigned base = 0;
    if (tid == 0) base = *(volatile unsigned*)&d_gen;
    base = __shfl_sync(0xffffffffu, base, 0);          // broadcast within warp0
    __shared__ unsigned sh_base;
    if (tid == 0) sh_base = base;
    // (synced by the __syncthreads below)

    // ---- Phase A (CTA-local): build SMEM cost slices from point clouds ----
    {
        const float tx = tgt[row * 3 + 0], ty = tgt[row * 3 + 1], tz = tgt[row * 3 + 2];
        for (int j = lane; j < Nn; j += 32) {
            const float dx = tx - outp[j * 3 + 0];
            const float dy = ty - outp[j * 3 + 1];
            const float dz = tz - outp[j * 3 + 2];
            sSC[(w << 10) + j] = S_CONST * (dx * dx + dy * dy + dz * dz);
        }
        const float ox = outp[row * 3 + 0], oy = outp[row * 3 + 1], oz = outp[row * 3 + 2];
        for (int i = lane; i < Nn; i += 32) {
            const float dx = tgt[i * 3 + 0] - ox;
            const float dy = tgt[i * 3 + 1] - oy;
            const float dz = tgt[i * 3 + 2] - oz;
            sSCT[(w << 10) + i] = S_CONST * (dx * dx + dy * dy + dz * dz);
        }
    }
    __syncthreads();
    base = sh_base;                                    // uniform across CTA

    // ---- Phase B: Sinkhorn iterations with exact-fixed-point early exit ----
    const int iters = iters_ptr ? iters_ptr[0] : 3000;
    unsigned kbar = 0;
    unsigned prev1 = 0xFFFFFFFFu, prev2 = 0xFFFFFFFFu; // bits of f_{it-1}, f_{it-2}
    int extra = -1;   // -1: normal; >=0: period-2 countdown of full iterations
    for (int it = 0; it < iters; it++) {
        const bool check = ((it & CHECK_MASK) == CHECK_MASK) && (extra < 0);
        const float fv = (it == 0)
            ? half_reduce<false>(sSC, (const float*)0, w, lane)
            : half_reduce<true >(sSC, d_Sg,            w, lane);
        const unsigned nb = __float_as_uint(fv);       // warp-uniform
        if (lane == 0) {
            d_Sf[row] = fv;                            // plain store, fenced in tree_sync
            if (check) {
                if (nb != prev1) d_flag1 = base + (unsigned)it;
                if (nb != prev2) d_flag2 = base + (unsigned)it;
            }
        }
        prev2 = prev1; prev1 = nb;
        tree_sync(base + (kbar++), gi);
        if (check) {
            const unsigned u1 = *(volatile unsigned*)&d_flag1;
            const unsigned u2 = *(volatile unsigned*)&d_flag2;
            if (u1 != base + (unsigned)it) break;      // f frozen => g already final
            if (u2 != base + (unsigned)it)             // bitwise period-2 cycle
                extra = (int)((unsigned)(iters - 1 - it) & 1u);
        }
        const float gv = half_reduce<true>(sSCT, d_Sf, w, lane);
        if (lane == 0) d_Sg[row] = gv;
        tree_sync(base + (kbar++), gi);
        if (extra == 0) break;                         // parity matched: done
        if (extra > 0) extra--;
    }

    // ---- Phase C: rowsum_i = sum_j exp2(Sf_i + Sg_j - SC_ij) * SC_ij ----
    {
        const float sfr = d_Sf[row];
        const float4* c4 = (const float4*)(sSC + (w << 10));
        const float4* g4 = (const float4*)d_Sg;
        float acc = 0.f;
#pragma unroll
        for (int kk = 0; kk < 8; kk++) {
            const int idx = (kk << 5) + lane;
            const float4 c = c4[idx];
            const float4 g = g4[idx];
            acc += ex2f(sfr + g.x - c.x) * c.x;
            acc += ex2f(sfr + g.y - c.y) * c.y;
            acc += ex2f(sfr + g.z - c.z) * c.z;
            acc += ex2f(sfr + g.w - c.w) * c.w;
        }
#pragma unroll
        for (int off = 16; off; off >>= 1)
            acc += __shfl_xor_sync(0xffffffffu, acc, off);
        if (lane == 0) d_rowsum[row] = acc;
    }
    tree_sync(base + (kbar++), gi);

    // ---- Deterministic final reduction by CTA 0; scale by 1/S ----
    if (bid == 0) {
        float v = 0.f;
        for (int i = tid; i < Nn; i += NTH) v += d_rowsum[i];
        red[tid] = v;
        __syncthreads();
        for (int s = NTH >> 1; s > 0; s >>= 1) {
            if (tid < s) red[tid] += red[tid + s];
            __syncthreads();
        }
        if (tid == 0) out[0] = red[0] * INV_S;
    }
    // Counters end at 0 (leaders reset each use); d_gen monotone with
    // per-launch base; flag tokens are launch-unique => replay-safe.
}

extern "C" void kernel_launch(void* const* d_in, const int* in_sizes, int n_in,
                              void* d_out, int out_size) {
    const float* tgt  = (const float*)d_in[0];
    const float* outp = (const float*)d_in[1];
    const int*   itp  = (n_in >= 3) ? (const int*)d_in[2] : nullptr;
    (void)in_sizes; (void)out_size;
    cudaFuncSetAttribute(emd_kernel, cudaFuncAttributeMaxDynamicSharedMemorySize,
                         SMEM_BYTES);
    emd_kernel<<<NCTA, NTH, SMEM_BYTES>>>(tgt, outp, itp, (float*)d_out);
}

// round 12
// speedup vs baseline: 1.4128x; 1.4128x over previous
#include <cuda_runtime.h>
#include <cuda_bf16.h>

// Sinkhorn EMD, N=M=1024, D=3, eps=0.01, iters read from input (3000).
// Persistent kernel, 128 CTAs x 256 threads; warp w of CTA b owns row b*8+w.
//
// Evolution of the PROVEN R9/R10 design (passed, 16.21ms, rel_err 1.1e-7):
//  * Cost matrix in SMEM (64KB/CTA, built locally in Phase A).
//  * Grid barrier now uses ONE membar.gl instead of two, and a FLAT monotone
//    arrival counter instead of the tree (R10 showed arrival serialization is
//    negligible; the tree's chained leader atomic only added latency):
//      __syncthreads
//      [tid0] __threadfence   // drains this CTA's publishes to L2 AND
//                             // invalidates L1 (CCTL.IVALL)
//      [tid0] prev = atomicAdd(&d_cnt, 1)          // monotone
//      [tid0] if (prev == m*NCTA + NCTA-1) d_gen = m+1   // release
//      [tid0] while (d_gen != m+1) spin            // volatile, L1-bypass
//      __syncthreads
//    Reader freshness after the spin comes from the SAME fence's IVALL:
//    between it and the post-barrier staging loads, nothing refetches the
//    f/g lines (spin touches only d_gen; other warps are held at the BAR,
//    which R9/R10 empirically show does not let global loads issue early;
//    pre-barrier loads' L1 fills completed before BAR entry).
//  * d_cnt/d_gen are monotone; per-launch base is snapshotted from d_gen in
//    Phase A (safe: d_gen cannot advance past base before ALL CTAs arrive at
//    barrier 0, which is after every CTA's snapshot). Equality spins are
//    wrap-safe. No reset, no handshake => graph-replay safe.
//  * Early-exit machinery from R11 removed (it never fired; pure overhead).
//
// Math in the exp2 domain scaled by S = log2(e)/eps (S*eps*ln2 == 1,
// S*eps*ln(1024) == 10):  S*f_row = -10 - m - log2(sum_j exp2(args_j - m)).

#define Nn      1024
#define NCTA    128
#define NTH     256
#define S_CONST 144.26950408889634074f   // log2(e)/eps, eps = 0.01
#define INV_S   0.0069314718055994531f   // eps*ln2 = 1/S

#define SMEM_BYTES (8 * 1024 * 2 * 4)    // sSC + sSCT = 64 KB

__device__ __align__(16) float d_Sf[Nn];      // S * f
__device__ __align__(16) float d_Sg[Nn];      // S * g
__device__ __align__(16) float d_rowsum[Nn];
__device__ unsigned d_cnt = 0;                 // monotone arrival counter
__device__ unsigned d_gen = 0;                 // monotone release word

__device__ __forceinline__ float ex2f(float x) {
    float r;
    asm("ex2.approx.ftz.f32 %0, %1;" : "=f"(r) : "f"(x));
    return r;
}

// Flat single-fence grid barrier. m = absolute barrier index (monotone
// across graph replays). Wrap-safe (equality comparisons only).
__device__ __forceinline__ void grid_bar(unsigned m) {
    __syncthreads();
    if (threadIdx.x == 0) {
        __threadfence();                           // drain publishes + IVALL
        const unsigned want = m + 1u;
        unsigned prev = atomicAdd(&d_cnt, 1u);
        if (prev == m * (unsigned)NCTA + (unsigned)(NCTA - 1))
            *(volatile unsigned*)&d_gen = want;    // release (last arrival)
        while (*(volatile unsigned*)&d_gen != want) { }
    }
    __syncthreads();
}

// One Sinkhorn half-update, warp-independent.
//   dout[row] = -10 - m - log2( sum_j exp2( din[j] - sC[w][j] - m ) )
template <bool HASG>
__device__ __forceinline__ void half_pass(const float* __restrict__ sC,
                                          const float* __restrict__ din, // global
                                          float* __restrict__ dout,      // global
                                          int w, int lane, int row) {
    const float4* c4 = (const float4*)(sC + (w << 10));
    const float4* g4 = (const float4*)din;
    float args[32];
    float m = -3.4e38f;
#pragma unroll
    for (int k = 0; k < 8; k++) {
        const int idx = (k << 5) + lane;
        const float4 c = c4[idx];                       // LDS.128, conflict-free
        const float4 g = HASG ? g4[idx]                 // plain LDG.128 (fresh post-IVALL)
                              : make_float4(0.f, 0.f, 0.f, 0.f);
        const float a0 = g.x - c.x;
        const float a1 = g.y - c.y;
        const float a2 = g.z - c.z;
        const float a3 = g.w - c.w;
        args[4 * k + 0] = a0; args[4 * k + 1] = a1;
        args[4 * k + 2] = a2; args[4 * k + 3] = a3;
        m = fmaxf(m, fmaxf(fmaxf(a0, a1), fmaxf(a2, a3)));
    }
#pragma unroll
    for (int off = 16; off; off >>= 1)
        m = fmaxf(m, __shfl_xor_sync(0xffffffffu, m, off));
    float sum = 0.f;
#pragma unroll
    for (int k = 0; k < 32; k++) sum += ex2f(args[k] - m);
#pragma unroll
    for (int off = 16; off; off >>= 1)
        sum += __shfl_xor_sync(0xffffffffu, sum, off);
    if (lane == 0)
        dout[row] = -10.0f - m - __log2f(sum);   // plain store, drained in grid_bar
}

__global__ void __launch_bounds__(NTH, 1)
emd_kernel(const float* __restrict__ tgt,    // [1024,3]
           const float* __restrict__ outp,   // [1024,3]
           const int*   __restrict__ iters_ptr,
           float*       __restrict__ out) {
    extern __shared__ __align__(16) float smem[];
    float* sSC  = smem;                // [8][1024]  S*C rows
    float* sSCT = smem + 8 * 1024;     // [8][1024]  S*C^T rows
    __shared__ float red[NTH];
    __shared__ unsigned sh_base;

    const int tid  = threadIdx.x;
    const int w    = tid >> 5;
    const int lane = tid & 31;
    const int bid  = (int)blockIdx.x;
    const int row  = (bid << 3) + w;

    // Per-launch base snapshot of the monotone release word (proven pattern).
    if (tid == 0) sh_base = *(volatile unsigned*)&d_gen;

    // ---- Phase A (CTA-local): build SMEM cost slices from point clouds ----
    {
        const float tx = tgt[row * 3 + 0], ty = tgt[row * 3 + 1], tz = tgt[row * 3 + 2];
        for (int j = lane; j < Nn; j += 32) {
            const float dx = tx - outp[j * 3 + 0];
            const float dy = ty - outp[j * 3 + 1];
            const float dz = tz - outp[j * 3 + 2];
            sSC[(w << 10) + j] = S_CONST * (dx * dx + dy * dy + dz * dz);
        }
        const float ox = outp[row * 3 + 0], oy = outp[row * 3 + 1], oz = outp[row * 3 + 2];
        for (int i = lane; i < Nn; i += 32) {
            const float dx = tgt[i * 3 + 0] - ox;
            const float dy = tgt[i * 3 + 1] - oy;
            const float dz = tgt[i * 3 + 2] - oz;
            sSCT[(w << 10) + i] = S_CONST * (dx * dx + dy * dy + dz * dz);
        }
    }
    __syncthreads();
    const unsigned base = sh_base;

    // ---- Phase B: Sinkhorn iterations ----
    const int iters = iters_ptr ? iters_ptr[0] : 3000;
    unsigned k = 0;
    {   // iteration 0: g == 0
        half_pass<false>(sSC, (const float*)0, d_Sf, w, lane, row);
        grid_bar(base + (k++));
        half_pass<true>(sSCT, d_Sf, d_Sg, w, lane, row);
        grid_bar(base + (k++));
    }
    for (int it = 1; it < iters; it++) {
        half_pass<true>(sSC,  d_Sg, d_Sf, w, lane, row);
        grid_bar(base + (k++));
        half_pass<true>(sSCT, d_Sf, d_Sg, w, lane, row);
        grid_bar(base + (k++));
    }

    // ---- Phase C: rowsum_i = sum_j exp2(Sf_i + Sg_j - SC_ij) * SC_ij ----
    {
        const float sfr = d_Sf[row];
        const float4* c4 = (const float4*)(sSC + (w << 10));
        const float4* g4 = (const float4*)d_Sg;
        float acc = 0.f;
#pragma unroll
        for (int kk = 0; kk < 8; kk++) {
            const int idx = (kk << 5) + lane;
            const float4 c = c4[idx];
            const float4 g = g4[idx];
            acc += ex2f(sfr + g.x - c.x) * c.x;
            acc += ex2f(sfr + g.y - c.y) * c.y;
            acc += ex2f(sfr + g.z - c.z) * c.z;
            acc += ex2f(sfr + g.w - c.w) * c.w;
        }
#pragma unroll
        for (int off = 16; off; off >>= 1)
            acc += __shfl_xor_sync(0xffffffffu, acc, off);
        if (lane == 0) d_rowsum[row] = acc;
    }
    grid_bar(base + (k++));

    // ---- Deterministic final reduction by CTA 0; scale by 1/S ----
    if (bid == 0) {
        float v = 0.f;
        for (int i = tid; i < Nn; i += NTH) v += d_rowsum[i];
        red[tid] = v;
        __syncthreads();
        for (int s = NTH >> 1; s > 0; s >>= 1) {
            if (tid < s) red[tid] += red[tid + s];
            __syncthreads();
        }
        if (tid == 0) out[0] = red[0] * INV_S;
    }
    // d_cnt and d_gen are monotone with a per-launch base snapshot and
    // equality spins => graph replays need no reset handshake.
}

extern "C" void kernel_launch(void* const* d_in, const int* in_sizes, int n_in,
                              void* d_out, int out_size) {
    const float* tgt  = (const float*)d_in[0];
    const float* outp = (const float*)d_in[1];
    const int*   itp  = (n_in >= 3) ? (const int*)d_in[2] : nullptr;
    (void)in_sizes; (void)out_size;
    cudaFuncSetAttribute(emd_kernel, cudaFuncAttributeMaxDynamicSharedMemorySize,
                         SMEM_BYTES);
    emd_kernel<<<NCTA, NTH, SMEM_BYTES>>>(tgt, outp, itp, (float*)d_out);
}